// round 9
// baseline (speedup 1.0000x reference)
#include <cuda_runtime.h>
#include <cuda_bf16.h>
#include <cstdint>

#define BB 4
#define NN 1024
#define DD 768
#define HH 12
#define HD 64
#define BH 48
#define KTH 104857

// ---------------- scratch ----------------
__device__ float g_attn[(size_t)48 * 1024 * 1024];     // fp32 scores
__device__ unsigned g_cand[(size_t)48 * 1048576];
__device__ unsigned g_hist[48 * 2048];
__device__ unsigned g_sel[48];
__device__ int g_krem[48];
__device__ float g_thr[48];
__device__ int g_bcnt[48 * 32];
// bf16 hi/lo operand storage
__device__ __nv_bfloat16 g_xh[4096 * 768], g_xl[4096 * 768];
__device__ __nv_bfloat16 g_wqh[2304 * 768], g_wql[2304 * 768];
__device__ __nv_bfloat16 g_woh[768 * 768], g_wol[768 * 768];
__device__ __nv_bfloat16 g_qh[(size_t)4096 * 2304], g_ql[(size_t)4096 * 2304];
__device__ __nv_bfloat16 g_ph[(size_t)48 * 1048576], g_pl[(size_t)48 * 1048576];
__device__ __nv_bfloat16 g_vth[48 * 65536], g_vtl[48 * 65536];
__device__ __nv_bfloat16 g_aoh[4096 * 768], g_aol[4096 * 768];

__device__ __forceinline__ unsigned fkey(float f) {
    unsigned u = __float_as_uint(f);
    return (u & 0x80000000u) ? ~u : (u ^ 0x80000000u);
}

// ---------------- cp.async + mma helpers ----------------
__device__ __forceinline__ void cp16(void* dst, const void* src) {
    unsigned d = (unsigned)__cvta_generic_to_shared(dst);
    asm volatile("cp.async.cg.shared.global [%0], [%1], 16;" :: "r"(d), "l"(src));
}
__device__ __forceinline__ void cp8(void* dst, const void* src) {
    unsigned d = (unsigned)__cvta_generic_to_shared(dst);
    asm volatile("cp.async.ca.shared.global [%0], [%1], 8;" :: "r"(d), "l"(src));
}
#define CPCOMMIT asm volatile("cp.async.commit_group;")
#define CPWAIT(N) asm volatile("cp.async.wait_group %0;" :: "n"(N))

__device__ __forceinline__ void mma_bf16(float* c, unsigned a0, unsigned a1,
                                         unsigned a2, unsigned a3,
                                         unsigned b0, unsigned b1) {
    asm volatile(
        "mma.sync.aligned.m16n8k16.row.col.f32.bf16.bf16.f32 "
        "{%0,%1,%2,%3}, {%4,%5,%6,%7}, {%8,%9}, {%0,%1,%2,%3};"
        : "+f"(c[0]), "+f"(c[1]), "+f"(c[2]), "+f"(c[3])
        : "r"(a0), "r"(a1), "r"(a2), "r"(a3), "r"(b0), "r"(b1));
}

// ---------------------------------------------------------------------------
// Pure-bf16 split GEMM: C = scale * A @ B^T (+bias).
// A: [M][K] k-contig hi/lo.  B: [N][K] k-contig hi/lo.  BK=16, double-buffered.
// SPLITOUT: write C as bf16 hi/lo; else fp32.
// ---------------------------------------------------------------------------
template <int NT, bool SPLITOUT, bool BIAS, bool SCALE>
__global__ void __launch_bounds__(256) mma_gemm(
    const __nv_bfloat16* __restrict__ Agh, const __nv_bfloat16* __restrict__ Agl,
    size_t azb, size_t azh, int lda,
    const __nv_bfloat16* __restrict__ Bgh, const __nv_bfloat16* __restrict__ Bgl,
    size_t bzb, size_t bzh, int ldb,
    const float* __restrict__ bias,
    float* __restrict__ C, __nv_bfloat16* __restrict__ Coh,
    __nv_bfloat16* __restrict__ Col,
    size_t czb, size_t czh, int ldc, int K, float scale) {
    constexpr int NI = NT / 32;
    __shared__ __nv_bfloat16 Ah[2][128][24], Al[2][128][24];
    __shared__ __nv_bfloat16 Bh[2][NT][24], Bl[2][NT][24];

    int t = threadIdx.x, lane = t & 31, warp = t >> 5;
    int z = blockIdx.z, zb = z / HH, zh = z % HH;
    Agh += (size_t)zb * azb + (size_t)zh * azh;
    Agl += (size_t)zb * azb + (size_t)zh * azh;
    Bgh += (size_t)zb * bzb + (size_t)zh * bzh;
    Bgl += (size_t)zb * bzb + (size_t)zh * bzh;
    int n0 = blockIdx.x * NT, m0 = blockIdx.y * 128;
    int wm = (warp >> 2) * 64, wn = (warp & 3) * (NT / 4);

    float c[4][NI][4];
#pragma unroll
    for (int mi = 0; mi < 4; mi++)
#pragma unroll
        for (int ni = 0; ni < NI; ni++)
#pragma unroll
            for (int q = 0; q < 4; q++) c[mi][ni][q] = 0.f;

    int arow = t >> 1, akc = (t & 1) * 8;
    int brow4 = t >> 2, bkc4 = (t & 3) * 4;

    auto stage = [&](int kt, int buf) {
        const __nv_bfloat16* ah = Agh + (size_t)(m0 + arow) * lda + kt * 16 + akc;
        const __nv_bfloat16* al = Agl + (size_t)(m0 + arow) * lda + kt * 16 + akc;
        cp16(&Ah[buf][arow][akc], ah);
        cp16(&Al[buf][arow][akc], al);
        if (NT == 128) {
            cp16(&Bh[buf][arow][akc],
                 Bgh + (size_t)(n0 + arow) * ldb + kt * 16 + akc);
            cp16(&Bl[buf][arow][akc],
                 Bgl + (size_t)(n0 + arow) * ldb + kt * 16 + akc);
        } else {
            cp8(&Bh[buf][brow4][bkc4],
                Bgh + (size_t)(n0 + brow4) * ldb + kt * 16 + bkc4);
            cp8(&Bl[buf][brow4][bkc4],
                Bgl + (size_t)(n0 + brow4) * ldb + kt * 16 + bkc4);
        }
    };

    int KT = K / 16;
    stage(0, 0);
    CPCOMMIT;
    for (int kt = 0; kt < KT; kt++) {
        int buf = kt & 1;
        if (kt + 1 < KT) { stage(kt + 1, buf ^ 1); CPCOMMIT; CPWAIT(1); }
        else { CPWAIT(0); }
        __syncthreads();

        unsigned bfh[NI][2], bfl[NI][2];
        int kk = (lane & 3) * 2;
#pragma unroll
        for (int ni = 0; ni < NI; ni++) {
            int n = wn + ni * 8 + (lane >> 2);
            bfh[ni][0] = *(const unsigned*)&Bh[buf][n][kk];
            bfh[ni][1] = *(const unsigned*)&Bh[buf][n][kk + 8];
            bfl[ni][0] = *(const unsigned*)&Bl[buf][n][kk];
            bfl[ni][1] = *(const unsigned*)&Bl[buf][n][kk + 8];
        }
#pragma unroll
        for (int mi = 0; mi < 4; mi++) {
            int r = wm + mi * 16 + (lane >> 2);
            unsigned a0h = *(const unsigned*)&Ah[buf][r][kk];
            unsigned a1h = *(const unsigned*)&Ah[buf][r + 8][kk];
            unsigned a2h = *(const unsigned*)&Ah[buf][r][kk + 8];
            unsigned a3h = *(const unsigned*)&Ah[buf][r + 8][kk + 8];
            unsigned a0l = *(const unsigned*)&Al[buf][r][kk];
            unsigned a1l = *(const unsigned*)&Al[buf][r + 8][kk];
            unsigned a2l = *(const unsigned*)&Al[buf][r][kk + 8];
            unsigned a3l = *(const unsigned*)&Al[buf][r + 8][kk + 8];
#pragma unroll
            for (int ni = 0; ni < NI; ni++) {
                mma_bf16(c[mi][ni], a0h, a1h, a2h, a3h, bfh[ni][0], bfh[ni][1]);
                mma_bf16(c[mi][ni], a0h, a1h, a2h, a3h, bfl[ni][0], bfl[ni][1]);
                mma_bf16(c[mi][ni], a0l, a1l, a2l, a3l, bfh[ni][0], bfh[ni][1]);
            }
        }
        __syncthreads();
    }

    // ---- epilogue
#pragma unroll
    for (int mi = 0; mi < 4; mi++) {
        int r = m0 + wm + mi * 16 + (lane >> 2);
#pragma unroll
        for (int ni = 0; ni < NI; ni++) {
            int col = n0 + wn + ni * 8 + (lane & 3) * 2;
            float v[4] = {c[mi][ni][0], c[mi][ni][1], c[mi][ni][2], c[mi][ni][3]};
            if (SCALE) {
#pragma unroll
                for (int q = 0; q < 4; q++) v[q] *= scale;
            }
            if (BIAS) {
                float2 bb = *(const float2*)(bias + col);
                v[0] += bb.x; v[1] += bb.y; v[2] += bb.x; v[3] += bb.y;
            }
            size_t o0 = (size_t)zb * czb + (size_t)zh * czh + (size_t)r * ldc + col;
            size_t o1 = o0 + (size_t)8 * ldc;
            if (SPLITOUT) {
                __nv_bfloat16 h0 = __float2bfloat16(v[0]);
                __nv_bfloat16 h1 = __float2bfloat16(v[1]);
                __nv_bfloat16 h2 = __float2bfloat16(v[2]);
                __nv_bfloat16 h3 = __float2bfloat16(v[3]);
                __nv_bfloat162 p01; p01.x = h0; p01.y = h1;
                __nv_bfloat162 p23; p23.x = h2; p23.y = h3;
                *(__nv_bfloat162*)(Coh + o0) = p01;
                *(__nv_bfloat162*)(Coh + o1) = p23;
                __nv_bfloat162 l01, l23;
                l01.x = __float2bfloat16(v[0] - __bfloat162float(h0));
                l01.y = __float2bfloat16(v[1] - __bfloat162float(h1));
                l23.x = __float2bfloat16(v[2] - __bfloat162float(h2));
                l23.y = __float2bfloat16(v[3] - __bfloat162float(h3));
                *(__nv_bfloat162*)(Col + o0) = l01;
                *(__nv_bfloat162*)(Col + o1) = l23;
            } else {
                *(float2*)(C + o0) = make_float2(v[0], v[1]);
                *(float2*)(C + o1) = make_float2(v[2], v[3]);
            }
        }
    }
}

// ---------------------------------------------------------------------------
// One-shot operand prep
// ---------------------------------------------------------------------------
__global__ void split_x(const float* __restrict__ in, __nv_bfloat16* __restrict__ oh,
                        __nv_bfloat16* __restrict__ ol) {
    int i = blockIdx.x * 256 + threadIdx.x;
    float4 v = ((const float4*)in)[i];
    float vv[4] = {v.x, v.y, v.z, v.w};
    __nv_bfloat16 h[4];
#pragma unroll
    for (int j = 0; j < 4; j++) h[j] = __float2bfloat16(vv[j]);
    __nv_bfloat162 h01; h01.x = h[0]; h01.y = h[1];
    __nv_bfloat162 h23; h23.x = h[2]; h23.y = h[3];
    *(__nv_bfloat162*)(oh + i * 4) = h01;
    *(__nv_bfloat162*)(oh + i * 4 + 2) = h23;
    __nv_bfloat162 l01, l23;
    l01.x = __float2bfloat16(vv[0] - __bfloat162float(h[0]));
    l01.y = __float2bfloat16(vv[1] - __bfloat162float(h[1]));
    l23.x = __float2bfloat16(vv[2] - __bfloat162float(h[2]));
    l23.y = __float2bfloat16(vv[3] - __bfloat162float(h[3]));
    *(__nv_bfloat162*)(ol + i * 4) = l01;
    *(__nv_bfloat162*)(ol + i * 4 + 2) = l23;
}

// transpose + split: out[n][k] (bf16 hi/lo) = in[k][n] (fp32)
__global__ void tr_split(const float* __restrict__ in, int ldin,
                         __nv_bfloat16* __restrict__ oh,
                         __nv_bfloat16* __restrict__ ol, int ldout) {
    __shared__ float tl[32][33];
    int n0 = blockIdx.x * 32, k0 = blockIdx.y * 32;
    int tx = threadIdx.x, ty = threadIdx.y;
#pragma unroll
    for (int i = 0; i < 4; i++)
        tl[ty + i * 8][tx] = in[(size_t)(k0 + ty + i * 8) * ldin + n0 + tx];
    __syncthreads();
#pragma unroll
    for (int i = 0; i < 4; i++) {
        float v = tl[tx][ty + i * 8];
        __nv_bfloat16 h = __float2bfloat16(v);
        size_t o = (size_t)(n0 + ty + i * 8) * ldout + k0 + tx;
        oh[o] = h;
        ol[o] = __float2bfloat16(v - __bfloat162float(h));
    }
}

// V transpose (bf16): vt[bh][d][m] = qkv[b][m][1536 + h*64 + d]
__global__ void tr_v() {
    __shared__ __nv_bfloat16 th[32][33], tle[32][33];
    int bh = blockIdx.z, b = bh / HH, h = bh % HH;
    int m0 = blockIdx.x * 32, d0 = blockIdx.y * 32;
    int tx = threadIdx.x, ty = threadIdx.y;
    const __nv_bfloat16* ih = g_qh + (size_t)b * 1024 * 2304 + 1536 + h * 64;
    const __nv_bfloat16* il = g_ql + (size_t)b * 1024 * 2304 + 1536 + h * 64;
#pragma unroll
    for (int i = 0; i < 4; i++) {
        th[ty + i * 8][tx] = ih[(size_t)(m0 + ty + i * 8) * 2304 + d0 + tx];
        tle[ty + i * 8][tx] = il[(size_t)(m0 + ty + i * 8) * 2304 + d0 + tx];
    }
    __syncthreads();
#pragma unroll
    for (int i = 0; i < 4; i++) {
        size_t o = (size_t)bh * 65536 + (size_t)(d0 + ty + i * 8) * 1024 + m0 + tx;
        g_vth[o] = th[tx][ty + i * 8];
        g_vtl[o] = tle[tx][ty + i * 8];
    }
}

// ---------------------------------------------------------------------------
// Selection (round-8 EXACT): init -> hist0 -> scan0 -> cand_seg -> sel_final
// ---------------------------------------------------------------------------
__global__ void sel_init() {
    int bh = blockIdx.x, t = threadIdx.x;
    for (int j = t; j < 2048; j += 256) g_hist[bh * 2048 + j] = 0u;
}

__global__ void hist0() {
    int bh = blockIdx.y, t = threadIdx.x;
    __shared__ unsigned sh[2048];
    for (int j = t; j < 2048; j += 256) sh[j] = 0u;
    __syncthreads();
    const float4* Sp = (const float4*)(g_attn + (size_t)bh * 1048576) +
                       (size_t)blockIdx.x * 8192;
    for (int i = 0; i < 32; i++) {
        float4 v = Sp[i * 256 + t];
        atomicAdd(&sh[fkey(v.x) >> 21], 1u);
        atomicAdd(&sh[fkey(v.y) >> 21], 1u);
        atomicAdd(&sh[fkey(v.z) >> 21], 1u);
        atomicAdd(&sh[fkey(v.w) >> 21], 1u);
    }
    __syncthreads();
    for (int j = t; j < 2048; j += 256) {
        unsigned cc = sh[j];
        if (cc) atomicAdd(&g_hist[bh * 2048 + j], cc);
    }
}

__global__ void scan0() {
    int bh = blockIdx.x, t = threadIdx.x;
    __shared__ unsigned ssum[256];
    __shared__ int s_sel;
    __shared__ unsigned s_kin;
    const unsigned* hist = g_hist + bh * 2048;
    unsigned loc[8], lsum = 0;
#pragma unroll
    for (int i = 0; i < 8; i++) { loc[i] = hist[t * 8 + i]; lsum += loc[i]; }
    ssum[t] = lsum;
    __syncthreads();
    if (t == 0) {
        unsigned k = KTH, cum = 0, kin = k;
        int sel = 255;
        for (int i = 0; i < 256; i++) {
            if (cum + ssum[i] >= k) { sel = i; kin = k - cum; break; }
            cum += ssum[i];
        }
        s_sel = sel; s_kin = kin;
    }
    __syncthreads();
    if (t == s_sel) {
        unsigned kk = s_kin, cum = 0, d = t * 8 + 7, knew = kk;
#pragma unroll
        for (int i = 0; i < 8; i++) {
            if (cum + loc[i] >= kk) { d = t * 8 + i; knew = kk - cum; break; }
            cum += loc[i];
        }
        g_sel[bh] = d;
        g_krem[bh] = (int)knew;
    }
}

__global__ void cand_seg() {
    __shared__ int s_cnt;
    int bh = blockIdx.y, t = threadIdx.x;
    unsigned lane = t & 31;
    if (t == 0) s_cnt = 0;
    __syncthreads();
    unsigned sel = g_sel[bh];
    unsigned* seg = g_cand + (size_t)bh * 1048576 + (size_t)blockIdx.x * 32768;
    const float4* Sp = (const float4*)(g_attn + (size_t)bh * 1048576) +
                       (size_t)blockIdx.x * 8192;
    for (int i = 0; i < 32; i++) {
        float4 v = Sp[i * 256 + t];
        unsigned key[4] = {fkey(v.x), fkey(v.y), fkey(v.z), fkey(v.w)};
#pragma unroll
        for (int j = 0; j < 4; j++) {
            bool m = (key[j] >> 21) == sel;
            unsigned bal = __ballot_sync(0xffffffffu, m);
            if (bal) {
                int leader = __ffs(bal) - 1;
                int base = 0;
                if ((int)lane == leader) base = atomicAdd(&s_cnt, __popc(bal));
                base = __shfl_sync(0xffffffffu, base, leader);
                if (m) seg[base + __popc(bal & ((1u << lane) - 1u))] = key[j];
            }
        }
    }
    __syncthreads();
    if (t == 0) g_bcnt[bh * 32 + blockIdx.x] = s_cnt;
}

__global__ void sel_final() {
    int bh = blockIdx.x, t = threadIdx.x;
    __shared__ unsigned sh[2048];
    __shared__ unsigned ssum[256];
    __shared__ int s_sel;
    __shared__ unsigned s_kin;
    __shared__ unsigned s_b1, s_k2;
    const unsigned* base = g_cand + (size_t)bh * 1048576;

    for (int j = t; j < 2048; j += 256) sh[j] = 0u;
    __syncthreads();
    for (int sg = 0; sg < 32; sg++) {
        int cnt = g_bcnt[bh * 32 + sg];
        const unsigned* cand = base + (size_t)sg * 32768;
        for (int i = t; i < cnt; i += 256)
            atomicAdd(&sh[(cand[i] >> 10) & 2047u], 1u);
    }
    __syncthreads();
    {
        unsigned loc[8], lsum = 0;
#pragma unroll
        for (int i = 0; i < 8; i++) { loc[i] = sh[t * 8 + i]; lsum += loc[i]; }
        ssum[t] = lsum;
        __syncthreads();
        if (t == 0) {
            unsigned k = (unsigned)g_krem[bh], cum = 0, kin = k;
            int sel = 255;
            for (int i = 0; i < 256; i++) {
                if (cum + ssum[i] >= k) { sel = i; kin = k - cum; break; }
                cum += ssum[i];
            }
            s_sel = sel; s_kin = kin;
        }
        __syncthreads();
        if (t == s_sel) {
            unsigned kk = s_kin, cum = 0, d = t * 8 + 7, knew = kk;
#pragma unroll
            for (int i = 0; i < 8; i++) {
                if (cum + loc[i] >= kk) { d = t * 8 + i; knew = kk - cum; break; }
                cum += loc[i];
            }
            s_b1 = d; s_k2 = knew;
        }
        __syncthreads();
    }
    unsigned b1 = s_b1;
    __syncthreads();

    for (int j = t; j < 1024; j += 256) sh[j] = 0u;
    __syncthreads();
    for (int sg = 0; sg < 32; sg++) {
        int cnt = g_bcnt[bh * 32 + sg];
        const unsigned* cand = base + (size_t)sg * 32768;
        for (int i = t; i < cnt; i += 256) {
            unsigned ky = cand[i];
            if (((ky >> 10) & 2047u) == b1) atomicAdd(&sh[ky & 1023u], 1u);
        }
    }
    __syncthreads();
    {
        unsigned loc[4], lsum = 0;
#pragma unroll
        for (int i = 0; i < 4; i++) { loc[i] = sh[t * 4 + i]; lsum += loc[i]; }
        ssum[t] = lsum;
        __syncthreads();
        if (t == 0) {
            unsigned k = s_k2, cum = 0, kin = k;
            int sel = 255;
            for (int i = 0; i < 256; i++) {
                if (cum + ssum[i] >= k) { sel = i; kin = k - cum; break; }
                cum += ssum[i];
            }
            s_sel = sel; s_kin = kin;
        }
        __syncthreads();
        if (t == s_sel) {
            unsigned kk = s_kin, cum = 0, d = t * 4 + 3;
#pragma unroll
            for (int i = 0; i < 4; i++) {
                if (cum + loc[i] >= kk) { d = t * 4 + i; break; }
                cum += loc[i];
            }
            unsigned key = (g_sel[bh] << 21) | (b1 << 10) | d;
            unsigned bits = (key & 0x80000000u) ? (key ^ 0x80000000u) : ~key;
            g_thr[bh] = __uint_as_float(bits);
        }
    }
}

// ---------------------------------------------------------------------------
// Masked softmax -> split bf16 P (hi/lo), one block per row
// ---------------------------------------------------------------------------
__global__ void softmax_split() {
    int row = blockIdx.x, bh = row >> 10;
    float thr = g_thr[bh];
    const float4* S = (const float4*)(g_attn + (size_t)row * NN);
    __nv_bfloat16* ph = g_ph + (size_t)row * NN;
    __nv_bfloat16* pl = g_pl + (size_t)row * NN;
    int t = threadIdx.x;
    unsigned lane = t & 31, w = t >> 5;
    __shared__ float red[8];

    float4 vv = S[t];
    float v[4] = {vv.x, vv.y, vv.z, vv.w};
    float mx = -3.0e38f;
#pragma unroll
    for (int i = 0; i < 4; i++) {
        v[i] = (v[i] <= thr) ? -1e9f : v[i];
        mx = fmaxf(mx, v[i]);
    }
#pragma unroll
    for (int o = 16; o; o >>= 1) mx = fmaxf(mx, __shfl_xor_sync(0xffffffffu, mx, o));
    if (lane == 0) red[w] = mx;
    __syncthreads();
    float m = red[0];
#pragma unroll
    for (int i = 1; i < 8; i++) m = fmaxf(m, red[i]);

    float e[4], s = 0.f;
#pragma unroll
    for (int i = 0; i < 4; i++) { e[i] = __expf(v[i] - m); s += e[i]; }
#pragma unroll
    for (int o = 16; o; o >>= 1) s += __shfl_xor_sync(0xffffffffu, s, o);
    __syncthreads();
    if (lane == 0) red[w] = s;
    __syncthreads();
    float tot = 0.f;
#pragma unroll
    for (int i = 0; i < 8; i++) tot += red[i];
    float inv = 1.f / tot;

    float p[4];
    __nv_bfloat16 h[4];
#pragma unroll
    for (int i = 0; i < 4; i++) { p[i] = e[i] * inv; h[i] = __float2bfloat16(p[i]); }
    __nv_bfloat162 h01; h01.x = h[0]; h01.y = h[1];
    __nv_bfloat162 h23; h23.x = h[2]; h23.y = h[3];
    *(__nv_bfloat162*)(ph + t * 4) = h01;
    *(__nv_bfloat162*)(ph + t * 4 + 2) = h23;
    __nv_bfloat162 l01, l23;
    l01.x = __float2bfloat16(p[0] - __bfloat162float(h[0]));
    l01.y = __float2bfloat16(p[1] - __bfloat162float(h[1]));
    l23.x = __float2bfloat16(p[2] - __bfloat162float(h[2]));
    l23.y = __float2bfloat16(p[3] - __bfloat162float(h[3]));
    *(__nv_bfloat162*)(pl + t * 4) = l01;
    *(__nv_bfloat162*)(pl + t * 4 + 2) = l23;
}

// ---------------------------------------------------------------------------
extern "C" void kernel_launch(void* const* d_in, const int* in_sizes, int n_in,
                              void* d_out, int out_size) {
    const float* x = (const float*)d_in[0];
    const float* W_qkv = (const float*)d_in[1];
    const float* b_qkv = (const float*)d_in[2];
    const float* W_out = (const float*)d_in[3];
    const float* b_out = (const float*)d_in[4];
    float* out = (float*)d_out;

    float* attn_p; cudaGetSymbolAddress((void**)&attn_p, g_attn);
    __nv_bfloat16 *xh, *xl, *wqh, *wql, *woh, *wol, *qh, *ql, *ph, *pl,
        *vth, *vtl, *aoh, *aol;
    cudaGetSymbolAddress((void**)&xh, g_xh);
    cudaGetSymbolAddress((void**)&xl, g_xl);
    cudaGetSymbolAddress((void**)&wqh, g_wqh);
    cudaGetSymbolAddress((void**)&wql, g_wql);
    cudaGetSymbolAddress((void**)&woh, g_woh);
    cudaGetSymbolAddress((void**)&wol, g_wol);
    cudaGetSymbolAddress((void**)&qh, g_qh);
    cudaGetSymbolAddress((void**)&ql, g_ql);
    cudaGetSymbolAddress((void**)&ph, g_ph);
    cudaGetSymbolAddress((void**)&pl, g_pl);
    cudaGetSymbolAddress((void**)&vth, g_vth);
    cudaGetSymbolAddress((void**)&vtl, g_vtl);
    cudaGetSymbolAddress((void**)&aoh, g_aoh);
    cudaGetSymbolAddress((void**)&aol, g_aol);

    dim3 tb(32, 8);
    // 0. operand prep + hist zero
    sel_init<<<BH, 256>>>();
    split_x<<<3072, 256>>>(x, xh, xl);
    tr_split<<<dim3(72, 24), tb>>>(W_qkv, 2304, wqh, wql, 768);
    tr_split<<<dim3(24, 24), tb>>>(W_out, 768, woh, wol, 768);
    // 1. QKV projection -> bf16 hi/lo qkv
    mma_gemm<128, true, true, false><<<dim3(18, 32, 1), 256>>>(
        xh, xl, 0, 0, 768, wqh, wql, 0, 0, 768, b_qkv,
        nullptr, qh, ql, 0, 0, 2304, 768, 1.f);
    // 1b. V transpose (k-major for AV)
    tr_v<<<dim3(32, 2, BH), tb>>>();
    // 2. Scores -> fp32 S
    mma_gemm<128, false, false, true><<<dim3(8, 8, BH), 256>>>(
        qh, ql, (size_t)1024 * 2304, 64, 2304,
        qh + 768, ql + 768, (size_t)1024 * 2304, 64, 2304, nullptr,
        attn_p, nullptr, nullptr, (size_t)HH * 1048576, 1048576, 1024, 64, 0.125f);
    // 3. Threshold
    hist0<<<dim3(32, BH), 256>>>();
    scan0<<<BH, 256>>>();
    cand_seg<<<dim3(32, BH), 256>>>();
    sel_final<<<BH, 256>>>();
    // 4. Masked softmax -> bf16 hi/lo P
    softmax_split<<<BH * NN, 256>>>();
    // 5. P @ V -> bf16 hi/lo AO
    mma_gemm<64, true, false, false><<<dim3(1, 8, BH), 256>>>(
        ph, pl, (size_t)HH * 1048576, 1048576, 1024,
        vth, vtl, (size_t)HH * 65536, 65536, 1024, nullptr,
        nullptr, aoh, aol, (size_t)1024 * 768, 64, 768, 1024, 1.f);
    // 6. Output projection -> fp32 out
    mma_gemm<128, false, true, false><<<dim3(6, 32, 1), 256>>>(
        aoh, aol, 0, 0, 768, woh, wol, 0, 0, 768, b_out,
        out, nullptr, nullptr, 0, 0, 768, 768, 1.f);
}

// round 11
// speedup vs baseline: 1.1979x; 1.1979x over previous
#include <cuda_runtime.h>
#include <cuda_bf16.h>
#include <cstdint>

#define BB 4
#define NN 1024
#define DD 768
#define HH 12
#define HD 64
#define BH 48
#define KTH 104857

// ---------------- scratch ----------------
__device__ float g_qkv[4096 * 2304];
__device__ float g_attn[(size_t)48 * 1024 * 1024];
__device__ float g_ao[4096 * 768];
__device__ unsigned g_hist[48 * 2048];
__device__ unsigned g_sel[48];
__device__ int g_krem[48];
__device__ float g_thr[48];
__device__ unsigned g_cand[(size_t)48 * 1048576];
__device__ int g_bcnt[48 * 32];

__device__ __forceinline__ unsigned fkey(float f) {
    unsigned u = __float_as_uint(f);
    return (u & 0x80000000u) ? ~u : (u ^ 0x80000000u);
}

// ---------------- bf16 mma helpers ----------------
__device__ __forceinline__ void mma_bf16(float* c, unsigned a0, unsigned a1,
                                         unsigned a2, unsigned a3,
                                         unsigned b0, unsigned b1) {
    asm volatile(
        "mma.sync.aligned.m16n8k16.row.col.f32.bf16.bf16.f32 "
        "{%0,%1,%2,%3}, {%4,%5,%6,%7}, {%8,%9}, {%0,%1,%2,%3};"
        : "+f"(c[0]), "+f"(c[1]), "+f"(c[2]), "+f"(c[3])
        : "r"(a0), "r"(a1), "r"(a2), "r"(a3), "r"(b0), "r"(b1));
}

// ---------------------------------------------------------------------------
// Split-bf16 tensor-core GEMM with REGISTER-PREFETCH pipelining.
// C[m,n] = scale * sum_k A[m,k]*Bop[k,n] (+bias)
// A: [M][K] k-contig. If TRANSB: B global is [K][N] n-contig (weights / V).
// Else: B global is [N][K] k-contig (scores). NT = N block tile.
// Block tile 128 x NT, BK=16, 256 threads (8 warps of 64 x NT/4).
// ---------------------------------------------------------------------------
template <int NT, bool TRANSB, bool BIAS, bool SCALE>
__global__ void __launch_bounds__(256) mma_gemm(
    const float* __restrict__ A, size_t azb, size_t azh, int lda,
    const float* __restrict__ B, size_t bzb, size_t bzh, int ldb,
    const float* __restrict__ bias, float* __restrict__ C,
    size_t czb, size_t czh, int ldc, int K, float scale) {
    constexpr int NI = NT / 32;
    constexpr int BPER = TRANSB ? (NT / 16) : 8;  // floats per thread for B
    __shared__ __nv_bfloat16 Ah[128][18], Al[128][18];
    __shared__ __nv_bfloat16 Bhs[NT][18], Bls[NT][18];

    int t = threadIdx.x, lane = t & 31, warp = t >> 5;
    int z = blockIdx.z, zb = z / HH, zh = z % HH;
    A += (size_t)zb * azb + (size_t)zh * azh;
    B += (size_t)zb * bzb + (size_t)zh * bzh;
    C += (size_t)zb * czb + (size_t)zh * czh;
    int n0 = blockIdx.x * NT, m0 = blockIdx.y * 128;
    int wm = (warp >> 2) * 64, wn = (warp & 3) * (NT / 4);

    float c[4][NI][4];
#pragma unroll
    for (int mi = 0; mi < 4; mi++)
#pragma unroll
        for (int ni = 0; ni < NI; ni++)
#pragma unroll
            for (int q = 0; q < 4; q++) c[mi][ni][q] = 0.f;

    int arow = t >> 1, akc = (t & 1) * 8;
    int bkr = t >> 4, bnc = (t & 15) * BPER;

    float ar[8], br[BPER];

    auto loadA = [&](int kt) {
        const float* Ap = A + (size_t)(m0 + arow) * lda + kt * 16 + akc;
        float4 v0 = *(const float4*)Ap;
        float4 v1 = *(const float4*)(Ap + 4);
        ar[0] = v0.x; ar[1] = v0.y; ar[2] = v0.z; ar[3] = v0.w;
        ar[4] = v1.x; ar[5] = v1.y; ar[6] = v1.z; ar[7] = v1.w;
    };
    auto loadB = [&](int kt) {
        if (TRANSB) {
            const float* Bp = B + (size_t)(kt * 16 + bkr) * ldb + n0 + bnc;
#pragma unroll
            for (int j4 = 0; j4 < BPER; j4 += 4) {
                float4 v = *(const float4*)(Bp + j4);
                br[j4 + 0] = v.x; br[j4 + 1] = v.y;
                br[j4 + 2] = v.z; br[j4 + 3] = v.w;
            }
        } else {
            const float* Bp = B + (size_t)(n0 + arow) * ldb + kt * 16 + akc;
            float4 v0 = *(const float4*)Bp;
            float4 v1 = *(const float4*)(Bp + 4);
            br[0] = v0.x; br[1] = v0.y; br[2] = v0.z; br[3] = v0.w;
            br[4] = v1.x; br[5] = v1.y; br[6] = v1.z; br[7] = v1.w;
        }
    };

    int KT = K / 16;
    loadA(0);
    loadB(0);
    for (int kt = 0; kt < KT; kt++) {
        // ---- convert regs -> smem (smem free: prior iter ended with sync)
#pragma unroll
        for (int j = 0; j < 8; j++) {
            __nv_bfloat16 h = __float2bfloat16(ar[j]);
            Ah[arow][akc + j] = h;
            Al[arow][akc + j] = __float2bfloat16(ar[j] - __bfloat162float(h));
        }
        if (TRANSB) {
#pragma unroll
            for (int j = 0; j < BPER; j++) {
                __nv_bfloat16 h = __float2bfloat16(br[j]);
                Bhs[bnc + j][bkr] = h;
                Bls[bnc + j][bkr] = __float2bfloat16(br[j] - __bfloat162float(h));
            }
        } else {
#pragma unroll
            for (int j = 0; j < 8; j++) {
                __nv_bfloat16 h = __float2bfloat16(br[j]);
                Bhs[arow][akc + j] = h;
                Bls[arow][akc + j] = __float2bfloat16(br[j] - __bfloat162float(h));
            }
        }
        __syncthreads();

        // ---- prefetch next tile's operands into registers (hidden by MMAs)
        if (kt + 1 < KT) { loadA(kt + 1); loadB(kt + 1); }

        // ---- fragments + mma
        unsigned bfh[NI][2], bfl[NI][2];
        int kk = (lane & 3) * 2;
#pragma unroll
        for (int ni = 0; ni < NI; ni++) {
            int n = wn + ni * 8 + (lane >> 2);
            bfh[ni][0] = *(const unsigned*)&Bhs[n][kk];
            bfh[ni][1] = *(const unsigned*)&Bhs[n][kk + 8];
            bfl[ni][0] = *(const unsigned*)&Bls[n][kk];
            bfl[ni][1] = *(const unsigned*)&Bls[n][kk + 8];
        }
#pragma unroll
        for (int mi = 0; mi < 4; mi++) {
            int r = wm + mi * 16 + (lane >> 2);
            unsigned a0h = *(const unsigned*)&Ah[r][kk];
            unsigned a1h = *(const unsigned*)&Ah[r + 8][kk];
            unsigned a2h = *(const unsigned*)&Ah[r][kk + 8];
            unsigned a3h = *(const unsigned*)&Ah[r + 8][kk + 8];
            unsigned a0l = *(const unsigned*)&Al[r][kk];
            unsigned a1l = *(const unsigned*)&Al[r + 8][kk];
            unsigned a2l = *(const unsigned*)&Al[r][kk + 8];
            unsigned a3l = *(const unsigned*)&Al[r + 8][kk + 8];
#pragma unroll
            for (int ni = 0; ni < NI; ni++) {
                mma_bf16(c[mi][ni], a0h, a1h, a2h, a3h, bfh[ni][0], bfh[ni][1]);
                mma_bf16(c[mi][ni], a0h, a1h, a2h, a3h, bfl[ni][0], bfl[ni][1]);
                mma_bf16(c[mi][ni], a0l, a1l, a2l, a3l, bfh[ni][0], bfh[ni][1]);
            }
        }
        __syncthreads();
    }

    // ---- epilogue
#pragma unroll
    for (int mi = 0; mi < 4; mi++) {
        int r = m0 + wm + mi * 16 + (lane >> 2);
#pragma unroll
        for (int ni = 0; ni < NI; ni++) {
            int col = n0 + wn + ni * 8 + (lane & 3) * 2;
            float2 v0 = {c[mi][ni][0], c[mi][ni][1]};
            float2 v1 = {c[mi][ni][2], c[mi][ni][3]};
            if (SCALE) {
                v0.x *= scale; v0.y *= scale;
                v1.x *= scale; v1.y *= scale;
            }
            if (BIAS) {
                float2 bb = *(const float2*)(bias + col);
                v0.x += bb.x; v0.y += bb.y;
                v1.x += bb.x; v1.y += bb.y;
            }
            *(float2*)(C + (size_t)r * ldc + col) = v0;
            *(float2*)(C + (size_t)(r + 8) * ldc + col) = v1;
        }
    }
}

// ---------------------------------------------------------------------------
// Selection: init -> hist0 -> scan0 -> segmented cand gather -> final select
// ---------------------------------------------------------------------------
__global__ void sel_init() {
    int bh = blockIdx.x, t = threadIdx.x;
    for (int j = t; j < 2048; j += 256) g_hist[bh * 2048 + j] = 0u;
}

__global__ void hist0() {
    int bh = blockIdx.y, t = threadIdx.x;
    __shared__ unsigned sh[2048];
    for (int j = t; j < 2048; j += 256) sh[j] = 0u;
    __syncthreads();
    const float4* Sp = (const float4*)(g_attn + (size_t)bh * 1048576) +
                       (size_t)blockIdx.x * 8192;
    for (int i = 0; i < 32; i++) {
        float4 v = Sp[i * 256 + t];
        atomicAdd(&sh[fkey(v.x) >> 21], 1u);
        atomicAdd(&sh[fkey(v.y) >> 21], 1u);
        atomicAdd(&sh[fkey(v.z) >> 21], 1u);
        atomicAdd(&sh[fkey(v.w) >> 21], 1u);
    }
    __syncthreads();
    for (int j = t; j < 2048; j += 256) {
        unsigned cc = sh[j];
        if (cc) atomicAdd(&g_hist[bh * 2048 + j], cc);
    }
}

__global__ void scan0() {
    int bh = blockIdx.x, t = threadIdx.x;
    __shared__ unsigned ssum[256];
    __shared__ int s_sel;
    __shared__ unsigned s_kin;
    const unsigned* hist = g_hist + bh * 2048;
    unsigned loc[8], lsum = 0;
#pragma unroll
    for (int i = 0; i < 8; i++) { loc[i] = hist[t * 8 + i]; lsum += loc[i]; }
    ssum[t] = lsum;
    __syncthreads();
    if (t == 0) {
        unsigned k = KTH, cum = 0, kin = k;
        int sel = 255;
        for (int i = 0; i < 256; i++) {
            if (cum + ssum[i] >= k) { sel = i; kin = k - cum; break; }
            cum += ssum[i];
        }
        s_sel = sel; s_kin = kin;
    }
    __syncthreads();
    if (t == s_sel) {
        unsigned kk = s_kin, cum = 0, d = t * 8 + 7, knew = kk;
#pragma unroll
        for (int i = 0; i < 8; i++) {
            if (cum + loc[i] >= kk) { d = t * 8 + i; knew = kk - cum; break; }
            cum += loc[i];
        }
        g_sel[bh] = d;
        g_krem[bh] = (int)knew;
    }
}

__global__ void cand_seg() {
    __shared__ int s_cnt;
    int bh = blockIdx.y, t = threadIdx.x;
    unsigned lane = t & 31;
    if (t == 0) s_cnt = 0;
    __syncthreads();
    unsigned sel = g_sel[bh];
    unsigned* seg = g_cand + (size_t)bh * 1048576 + (size_t)blockIdx.x * 32768;
    const float4* Sp = (const float4*)(g_attn + (size_t)bh * 1048576) +
                       (size_t)blockIdx.x * 8192;
    for (int i = 0; i < 32; i++) {
        float4 v = Sp[i * 256 + t];
        unsigned key[4] = {fkey(v.x), fkey(v.y), fkey(v.z), fkey(v.w)};
#pragma unroll
        for (int j = 0; j < 4; j++) {
            bool m = (key[j] >> 21) == sel;
            unsigned bal = __ballot_sync(0xffffffffu, m);
            if (bal) {
                int leader = __ffs(bal) - 1;
                int base = 0;
                if ((int)lane == leader) base = atomicAdd(&s_cnt, __popc(bal));
                base = __shfl_sync(0xffffffffu, base, leader);
                if (m) seg[base + __popc(bal & ((1u << lane) - 1u))] = key[j];
            }
        }
    }
    __syncthreads();
    if (t == 0) g_bcnt[bh * 32 + blockIdx.x] = s_cnt;
}

__global__ void sel_final() {
    int bh = blockIdx.x, t = threadIdx.x;
    __shared__ unsigned sh[2048];
    __shared__ unsigned ssum[256];
    __shared__ int s_sel;
    __shared__ unsigned s_kin;
    __shared__ unsigned s_b1, s_k2;
    const unsigned* base = g_cand + (size_t)bh * 1048576;

    // pass A: bits 20..10
    for (int j = t; j < 2048; j += 256) sh[j] = 0u;
    __syncthreads();
    for (int sg = 0; sg < 32; sg++) {
        int cnt = g_bcnt[bh * 32 + sg];
        const unsigned* cand = base + (size_t)sg * 32768;
        for (int i = t; i < cnt; i += 256)
            atomicAdd(&sh[(cand[i] >> 10) & 2047u], 1u);
    }
    __syncthreads();
    {
        unsigned loc[8], lsum = 0;
#pragma unroll
        for (int i = 0; i < 8; i++) { loc[i] = sh[t * 8 + i]; lsum += loc[i]; }
        ssum[t] = lsum;
        __syncthreads();
        if (t == 0) {
            unsigned k = (unsigned)g_krem[bh], cum = 0, kin = k;
            int sel = 255;
            for (int i = 0; i < 256; i++) {
                if (cum + ssum[i] >= k) { sel = i; kin = k - cum; break; }
                cum += ssum[i];
            }
            s_sel = sel; s_kin = kin;
        }
        __syncthreads();
        if (t == s_sel) {
            unsigned kk = s_kin, cum = 0, d = t * 8 + 7, knew = kk;
#pragma unroll
            for (int i = 0; i < 8; i++) {
                if (cum + loc[i] >= kk) { d = t * 8 + i; knew = kk - cum; break; }
                cum += loc[i];
            }
            s_b1 = d; s_k2 = knew;
        }
        __syncthreads();
    }
    unsigned b1 = s_b1;
    __syncthreads();

    // pass B: bits 9..0
    for (int j = t; j < 1024; j += 256) sh[j] = 0u;
    __syncthreads();
    for (int sg = 0; sg < 32; sg++) {
        int cnt = g_bcnt[bh * 32 + sg];
        const unsigned* cand = base + (size_t)sg * 32768;
        for (int i = t; i < cnt; i += 256) {
            unsigned ky = cand[i];
            if (((ky >> 10) & 2047u) == b1) atomicAdd(&sh[ky & 1023u], 1u);
        }
    }
    __syncthreads();
    {
        unsigned loc[4], lsum = 0;
#pragma unroll
        for (int i = 0; i < 4; i++) { loc[i] = sh[t * 4 + i]; lsum += loc[i]; }
        ssum[t] = lsum;
        __syncthreads();
        if (t == 0) {
            unsigned k = s_k2, cum = 0, kin = k;
            int sel = 255;
            for (int i = 0; i < 256; i++) {
                if (cum + ssum[i] >= k) { sel = i; kin = k - cum; break; }
                cum += ssum[i];
            }
            s_sel = sel; s_kin = kin;
        }
        __syncthreads();
        if (t == s_sel) {
            unsigned kk = s_kin, cum = 0, d = t * 4 + 3;
#pragma unroll
            for (int i = 0; i < 4; i++) {
                if (cum + loc[i] >= kk) { d = t * 4 + i; break; }
                cum += loc[i];
            }
            unsigned key = (g_sel[bh] << 21) | (b1 << 10) | d;
            unsigned bits = (key & 0x80000000u) ? (key ^ 0x80000000u) : ~key;
            g_thr[bh] = __uint_as_float(bits);
        }
    }
}

// ---------------------------------------------------------------------------
// Masked softmax (float4, one block per row, in place)
// ---------------------------------------------------------------------------
__global__ void softmax_mask() {
    int row = blockIdx.x, bh = row >> 10;
    float thr = g_thr[bh];
    float4* S = (float4*)(g_attn + (size_t)row * NN);
    int t = threadIdx.x;
    unsigned lane = t & 31, w = t >> 5;
    __shared__ float red[8];

    float4 vv = S[t];
    float v[4] = {vv.x, vv.y, vv.z, vv.w};
    float mx = -3.0e38f;
#pragma unroll
    for (int i = 0; i < 4; i++) {
        v[i] = (v[i] <= thr) ? -1e9f : v[i];
        mx = fmaxf(mx, v[i]);
    }
#pragma unroll
    for (int o = 16; o; o >>= 1) mx = fmaxf(mx, __shfl_xor_sync(0xffffffffu, mx, o));
    if (lane == 0) red[w] = mx;
    __syncthreads();
    float m = red[0];
#pragma unroll
    for (int i = 1; i < 8; i++) m = fmaxf(m, red[i]);

    float e[4], s = 0.f;
#pragma unroll
    for (int i = 0; i < 4; i++) { e[i] = __expf(v[i] - m); s += e[i]; }
#pragma unroll
    for (int o = 16; o; o >>= 1) s += __shfl_xor_sync(0xffffffffu, s, o);
    __syncthreads();
    if (lane == 0) red[w] = s;
    __syncthreads();
    float tot = 0.f;
#pragma unroll
    for (int i = 0; i < 8; i++) tot += red[i];
    float inv = 1.f / tot;
    float4 ov = {e[0] * inv, e[1] * inv, e[2] * inv, e[3] * inv};
    S[t] = ov;
}

// ---------------------------------------------------------------------------
extern "C" void kernel_launch(void* const* d_in, const int* in_sizes, int n_in,
                              void* d_out, int out_size) {
    const float* x = (const float*)d_in[0];
    const float* W_qkv = (const float*)d_in[1];
    const float* b_qkv = (const float*)d_in[2];
    const float* W_out = (const float*)d_in[3];
    const float* b_out = (const float*)d_in[4];
    float* out = (float*)d_out;

    float* qkv_p; cudaGetSymbolAddress((void**)&qkv_p, g_qkv);
    float* attn_p; cudaGetSymbolAddress((void**)&attn_p, g_attn);
    float* ao_p;  cudaGetSymbolAddress((void**)&ao_p, g_ao);

    // 0. zero hist
    sel_init<<<BH, 256>>>();
    // 1. QKV projection: [4096,768] @ W[768,2304] + bias
    mma_gemm<128, true, true, false><<<dim3(18, 32, 1), 256>>>(
        x, 0, 0, 768, W_qkv, 0, 0, 2304, b_qkv, qkv_p, 0, 0, 2304, 768, 1.f);
    // 2. Scores: Q @ K^T * 0.125
    mma_gemm<128, false, false, true><<<dim3(8, 8, BH), 256>>>(
        qkv_p, (size_t)1024 * 2304, 64, 2304,
        qkv_p + 768, (size_t)1024 * 2304, 64, 2304,
        nullptr, attn_p, (size_t)HH * 1048576, 1048576, 1024, 64, 0.125f);
    // 3. Threshold: hist + scan + segmented candidate gather + final select
    hist0<<<dim3(32, BH), 256>>>();
    scan0<<<BH, 256>>>();
    cand_seg<<<dim3(32, BH), 256>>>();
    sel_final<<<BH, 256>>>();
    // 4. Masked softmax in place
    softmax_mask<<<BH * NN, 256>>>();
    // 5. P @ V
    mma_gemm<64, true, false, false><<<dim3(1, 8, BH), 256>>>(
        attn_p, (size_t)HH * 1048576, 1048576, 1024,
        qkv_p + 1536, (size_t)1024 * 2304, 64, 2304,
        nullptr, ao_p, (size_t)1024 * 768, 64, 768, 1024, 1.f);
    // 6. Output projection: [4096,768] @ W[768,768] + bias
    mma_gemm<128, true, true, false><<<dim3(6, 32, 1), 256>>>(
        ao_p, 0, 0, 768, W_out, 0, 0, 768, b_out, out, 0, 0, 768, 768, 1.f);
}

// round 12
// speedup vs baseline: 1.2856x; 1.0732x over previous
#include <cuda_runtime.h>
#include <cuda_bf16.h>
#include <cstdint>

#define BB 4
#define NN 1024
#define DD 768
#define HH 12
#define HD 64
#define BH 48
#define KTH 104857

// ---------------- scratch ----------------
__device__ float g_qkv[4096 * 2304];
__device__ float g_attn[(size_t)48 * 1024 * 1024];
__device__ float g_ao[4096 * 768];
__device__ unsigned g_hist[48 * 2048];
__device__ unsigned g_sel[48];
__device__ int g_krem[48];
__device__ float g_thr[48];
__device__ unsigned g_cand[(size_t)48 * 1048576];
__device__ int g_bcnt[48 * 32];
__device__ float g_rowm[48 * 1024];
__device__ float g_rowinv[48 * 1024];

__device__ __forceinline__ unsigned fkey(float f) {
    unsigned u = __float_as_uint(f);
    return (u & 0x80000000u) ? ~u : (u ^ 0x80000000u);
}

// ---------------- bf16 mma helpers ----------------
__device__ __forceinline__ void mma_bf16(float* c, unsigned a0, unsigned a1,
                                         unsigned a2, unsigned a3,
                                         unsigned b0, unsigned b1) {
    asm volatile(
        "mma.sync.aligned.m16n8k16.row.col.f32.bf16.bf16.f32 "
        "{%0,%1,%2,%3}, {%4,%5,%6,%7}, {%8,%9}, {%0,%1,%2,%3};"
        : "+f"(c[0]), "+f"(c[1]), "+f"(c[2]), "+f"(c[3])
        : "r"(a0), "r"(a1), "r"(a2), "r"(a3), "r"(b0), "r"(b1));
}

// ---------------------------------------------------------------------------
// Split-bf16 tensor-core GEMM (round-8 proven mainloop).
// C[m,n] = scale * sum_k A[m,k]*Bop[k,n] (+bias)
// A: [M][K] k-contig. If TRANSB: B global is [K][N] n-contig (weights / V).
// Else: B global is [N][K] k-contig (scores). NT = N block tile.
// SMAX: A is raw scores; apply masked softmax inline using per-row stats.
// Block tile 128 x NT, BK=16, 256 threads (8 warps of 64 x NT/4).
// ---------------------------------------------------------------------------
template <int NT, bool TRANSB, bool BIAS, bool SCALE, bool SMAX>
__global__ void __launch_bounds__(256) mma_gemm(
    const float* __restrict__ A, size_t azb, size_t azh, int lda,
    const float* __restrict__ B, size_t bzb, size_t bzh, int ldb,
    const float* __restrict__ bias, float* __restrict__ C,
    size_t czb, size_t czh, int ldc, int K, float scale) {
    constexpr int NI = NT / 32;
    __shared__ __nv_bfloat16 Ah[128][18], Al[128][18];
    __shared__ __nv_bfloat16 Bhs[NT][18], Bls[NT][18];

    int t = threadIdx.x, lane = t & 31, warp = t >> 5;
    int z = blockIdx.z, zb = z / HH, zh = z % HH;
    A += (size_t)zb * azb + (size_t)zh * azh;
    B += (size_t)zb * bzb + (size_t)zh * bzh;
    C += (size_t)zb * czb + (size_t)zh * czh;
    int n0 = blockIdx.x * NT, m0 = blockIdx.y * 128;
    int wm = (warp >> 2) * 64, wn = (warp & 3) * (NT / 4);

    int arow = t >> 1, akc = (t & 1) * 8;

    // per-row softmax stats (loop-invariant: this thread stages row m0+arow)
    float s_thr = 0.f, s_m = 0.f, s_inv = 0.f;
    if (SMAX) {
        s_thr = g_thr[z];
        int grow = z * NN + m0 + arow;
        s_m = g_rowm[grow];
        s_inv = g_rowinv[grow];
    }

    float c[4][NI][4];
#pragma unroll
    for (int mi = 0; mi < 4; mi++)
#pragma unroll
        for (int ni = 0; ni < NI; ni++)
#pragma unroll
            for (int q = 0; q < 4; q++) c[mi][ni][q] = 0.f;

    for (int kt = 0; kt < K; kt += 16) {
        // ---- stage A: 128 x 16, split hi/lo (optionally softmax inline)
        {
            const float* Ap = A + (size_t)(m0 + arow) * lda + kt + akc;
            float4 v0 = *(const float4*)Ap;
            float4 v1 = *(const float4*)(Ap + 4);
            float vv[8] = {v0.x, v0.y, v0.z, v0.w, v1.x, v1.y, v1.z, v1.w};
            if (SMAX) {
#pragma unroll
                for (int j = 0; j < 8; j++) {
                    float vm = (vv[j] <= s_thr) ? -1e9f : vv[j];
                    vv[j] = __expf(vm - s_m) * s_inv;
                }
            }
#pragma unroll
            for (int j = 0; j < 8; j++) {
                __nv_bfloat16 h = __float2bfloat16(vv[j]);
                Ah[arow][akc + j] = h;
                Al[arow][akc + j] = __float2bfloat16(vv[j] - __bfloat162float(h));
            }
        }
        // ---- stage B
        if (TRANSB) {
            constexpr int PER = NT / 16;      // 8 (NT=128) or 4 (NT=64)
            int kr = t >> 4, nc = (t & 15) * PER;
            const float* Bp = B + (size_t)(kt + kr) * ldb + n0 + nc;
#pragma unroll
            for (int j4 = 0; j4 < PER; j4 += 4) {
                float4 v = *(const float4*)(Bp + j4);
                float vv[4] = {v.x, v.y, v.z, v.w};
#pragma unroll
                for (int j = 0; j < 4; j++) {
                    __nv_bfloat16 h = __float2bfloat16(vv[j]);
                    Bhs[nc + j4 + j][kr] = h;
                    Bls[nc + j4 + j][kr] =
                        __float2bfloat16(vv[j] - __bfloat162float(h));
                }
            }
        } else {
            // NT == 128: B global [N][K] k-contig
            int row = t >> 1, kc = (t & 1) * 8;
            const float* Bp = B + (size_t)(n0 + row) * ldb + kt + kc;
            float4 v0 = *(const float4*)Bp;
            float4 v1 = *(const float4*)(Bp + 4);
            float vv[8] = {v0.x, v0.y, v0.z, v0.w, v1.x, v1.y, v1.z, v1.w};
#pragma unroll
            for (int j = 0; j < 8; j++) {
                __nv_bfloat16 h = __float2bfloat16(vv[j]);
                Bhs[row][kc + j] = h;
                Bls[row][kc + j] = __float2bfloat16(vv[j] - __bfloat162float(h));
            }
        }
        __syncthreads();

        // ---- fragments + mma
        unsigned bfh[NI][2], bfl[NI][2];
        int kk = (lane & 3) * 2;
#pragma unroll
        for (int ni = 0; ni < NI; ni++) {
            int n = wn + ni * 8 + (lane >> 2);
            bfh[ni][0] = *(const unsigned*)&Bhs[n][kk];
            bfh[ni][1] = *(const unsigned*)&Bhs[n][kk + 8];
            bfl[ni][0] = *(const unsigned*)&Bls[n][kk];
            bfl[ni][1] = *(const unsigned*)&Bls[n][kk + 8];
        }
#pragma unroll
        for (int mi = 0; mi < 4; mi++) {
            int r = wm + mi * 16 + (lane >> 2);
            unsigned a0h = *(const unsigned*)&Ah[r][kk];
            unsigned a1h = *(const unsigned*)&Ah[r + 8][kk];
            unsigned a2h = *(const unsigned*)&Ah[r][kk + 8];
            unsigned a3h = *(const unsigned*)&Ah[r + 8][kk + 8];
            unsigned a0l = *(const unsigned*)&Al[r][kk];
            unsigned a1l = *(const unsigned*)&Al[r + 8][kk];
            unsigned a2l = *(const unsigned*)&Al[r][kk + 8];
            unsigned a3l = *(const unsigned*)&Al[r + 8][kk + 8];
#pragma unroll
            for (int ni = 0; ni < NI; ni++) {
                mma_bf16(c[mi][ni], a0h, a1h, a2h, a3h, bfh[ni][0], bfh[ni][1]);
                mma_bf16(c[mi][ni], a0h, a1h, a2h, a3h, bfl[ni][0], bfl[ni][1]);
                mma_bf16(c[mi][ni], a0l, a1l, a2l, a3l, bfh[ni][0], bfh[ni][1]);
            }
        }
        __syncthreads();
    }

    // ---- epilogue
#pragma unroll
    for (int mi = 0; mi < 4; mi++) {
        int r = m0 + wm + mi * 16 + (lane >> 2);
#pragma unroll
        for (int ni = 0; ni < NI; ni++) {
            int col = n0 + wn + ni * 8 + (lane & 3) * 2;
            float2 v0 = {c[mi][ni][0], c[mi][ni][1]};
            float2 v1 = {c[mi][ni][2], c[mi][ni][3]};
            if (SCALE) {
                v0.x *= scale; v0.y *= scale;
                v1.x *= scale; v1.y *= scale;
            }
            if (BIAS) {
                float2 bb = *(const float2*)(bias + col);
                v0.x += bb.x; v0.y += bb.y;
                v1.x += bb.x; v1.y += bb.y;
            }
            *(float2*)(C + (size_t)r * ldc + col) = v0;
            *(float2*)(C + (size_t)(r + 8) * ldc + col) = v1;
        }
    }
}

// ---------------------------------------------------------------------------
// Selection: init -> hist0 -> scan0 -> segmented cand gather -> final select
// ---------------------------------------------------------------------------
__global__ void sel_init() {
    int bh = blockIdx.x, t = threadIdx.x;
    for (int j = t; j < 2048; j += 256) g_hist[bh * 2048 + j] = 0u;
}

__global__ void hist0() {
    int bh = blockIdx.y, t = threadIdx.x;
    __shared__ unsigned sh[2048];
    for (int j = t; j < 2048; j += 256) sh[j] = 0u;
    __syncthreads();
    const float4* Sp = (const float4*)(g_attn + (size_t)bh * 1048576) +
                       (size_t)blockIdx.x * 8192;
    for (int i = 0; i < 32; i++) {
        float4 v = Sp[i * 256 + t];
        atomicAdd(&sh[fkey(v.x) >> 21], 1u);
        atomicAdd(&sh[fkey(v.y) >> 21], 1u);
        atomicAdd(&sh[fkey(v.z) >> 21], 1u);
        atomicAdd(&sh[fkey(v.w) >> 21], 1u);
    }
    __syncthreads();
    for (int j = t; j < 2048; j += 256) {
        unsigned cc = sh[j];
        if (cc) atomicAdd(&g_hist[bh * 2048 + j], cc);
    }
}

__global__ void scan0() {
    int bh = blockIdx.x, t = threadIdx.x;
    __shared__ unsigned ssum[256];
    __shared__ int s_sel;
    __shared__ unsigned s_kin;
    const unsigned* hist = g_hist + bh * 2048;
    unsigned loc[8], lsum = 0;
#pragma unroll
    for (int i = 0; i < 8; i++) { loc[i] = hist[t * 8 + i]; lsum += loc[i]; }
    ssum[t] = lsum;
    __syncthreads();
    if (t == 0) {
        unsigned k = KTH, cum = 0, kin = k;
        int sel = 255;
        for (int i = 0; i < 256; i++) {
            if (cum + ssum[i] >= k) { sel = i; kin = k - cum; break; }
            cum += ssum[i];
        }
        s_sel = sel; s_kin = kin;
    }
    __syncthreads();
    if (t == s_sel) {
        unsigned kk = s_kin, cum = 0, d = t * 8 + 7, knew = kk;
#pragma unroll
        for (int i = 0; i < 8; i++) {
            if (cum + loc[i] >= kk) { d = t * 8 + i; knew = kk - cum; break; }
            cum += loc[i];
        }
        g_sel[bh] = d;
        g_krem[bh] = (int)knew;
    }
}

__global__ void cand_seg() {
    __shared__ int s_cnt;
    int bh = blockIdx.y, t = threadIdx.x;
    unsigned lane = t & 31;
    if (t == 0) s_cnt = 0;
    __syncthreads();
    unsigned sel = g_sel[bh];
    unsigned* seg = g_cand + (size_t)bh * 1048576 + (size_t)blockIdx.x * 32768;
    const float4* Sp = (const float4*)(g_attn + (size_t)bh * 1048576) +
                       (size_t)blockIdx.x * 8192;
    for (int i = 0; i < 32; i++) {
        float4 v = Sp[i * 256 + t];
        unsigned key[4] = {fkey(v.x), fkey(v.y), fkey(v.z), fkey(v.w)};
#pragma unroll
        for (int j = 0; j < 4; j++) {
            bool m = (key[j] >> 21) == sel;
            unsigned bal = __ballot_sync(0xffffffffu, m);
            if (bal) {
                int leader = __ffs(bal) - 1;
                int base = 0;
                if ((int)lane == leader) base = atomicAdd(&s_cnt, __popc(bal));
                base = __shfl_sync(0xffffffffu, base, leader);
                if (m) seg[base + __popc(bal & ((1u << lane) - 1u))] = key[j];
            }
        }
    }
    __syncthreads();
    if (t == 0) g_bcnt[bh * 32 + blockIdx.x] = s_cnt;
}

__global__ void sel_final() {
    int bh = blockIdx.x, t = threadIdx.x;
    __shared__ unsigned sh[2048];
    __shared__ unsigned ssum[256];
    __shared__ int s_sel;
    __shared__ unsigned s_kin;
    __shared__ unsigned s_b1, s_k2;
    const unsigned* base = g_cand + (size_t)bh * 1048576;

    // pass A: bits 20..10
    for (int j = t; j < 2048; j += 256) sh[j] = 0u;
    __syncthreads();
    for (int sg = 0; sg < 32; sg++) {
        int cnt = g_bcnt[bh * 32 + sg];
        const unsigned* cand = base + (size_t)sg * 32768;
        for (int i = t; i < cnt; i += 256)
            atomicAdd(&sh[(cand[i] >> 10) & 2047u], 1u);
    }
    __syncthreads();
    {
        unsigned loc[8], lsum = 0;
#pragma unroll
        for (int i = 0; i < 8; i++) { loc[i] = sh[t * 8 + i]; lsum += loc[i]; }
        ssum[t] = lsum;
        __syncthreads();
        if (t == 0) {
            unsigned k = (unsigned)g_krem[bh], cum = 0, kin = k;
            int sel = 255;
            for (int i = 0; i < 256; i++) {
                if (cum + ssum[i] >= k) { sel = i; kin = k - cum; break; }
                cum += ssum[i];
            }
            s_sel = sel; s_kin = kin;
        }
        __syncthreads();
        if (t == s_sel) {
            unsigned kk = s_kin, cum = 0, d = t * 8 + 7, knew = kk;
#pragma unroll
            for (int i = 0; i < 8; i++) {
                if (cum + loc[i] >= kk) { d = t * 8 + i; knew = kk - cum; break; }
                cum += loc[i];
            }
            s_b1 = d; s_k2 = knew;
        }
        __syncthreads();
    }
    unsigned b1 = s_b1;
    __syncthreads();

    // pass B: bits 9..0
    for (int j = t; j < 1024; j += 256) sh[j] = 0u;
    __syncthreads();
    for (int sg = 0; sg < 32; sg++) {
        int cnt = g_bcnt[bh * 32 + sg];
        const unsigned* cand = base + (size_t)sg * 32768;
        for (int i = t; i < cnt; i += 256) {
            unsigned ky = cand[i];
            if (((ky >> 10) & 2047u) == b1) atomicAdd(&sh[ky & 1023u], 1u);
        }
    }
    __syncthreads();
    {
        unsigned loc[4], lsum = 0;
#pragma unroll
        for (int i = 0; i < 4; i++) { loc[i] = sh[t * 4 + i]; lsum += loc[i]; }
        ssum[t] = lsum;
        __syncthreads();
        if (t == 0) {
            unsigned k = s_k2, cum = 0, kin = k;
            int sel = 255;
            for (int i = 0; i < 256; i++) {
                if (cum + ssum[i] >= k) { sel = i; kin = k - cum; break; }
                cum += ssum[i];
            }
            s_sel = sel; s_kin = kin;
        }
        __syncthreads();
        if (t == s_sel) {
            unsigned kk = s_kin, cum = 0, d = t * 4 + 3;
#pragma unroll
            for (int i = 0; i < 4; i++) {
                if (cum + loc[i] >= kk) { d = t * 4 + i; break; }
                cum += loc[i];
            }
            unsigned key = (g_sel[bh] << 21) | (b1 << 10) | d;
            unsigned bits = (key & 0x80000000u) ? (key ^ 0x80000000u) : ~key;
            g_thr[bh] = __uint_as_float(bits);
        }
    }
}

// ---------------------------------------------------------------------------
// Row stats: identical math to the old softmax kernel, but writes only
// per-row (max, 1/sum). AV applies the softmax inline during staging.
// ---------------------------------------------------------------------------
__global__ void rowstats() {
    int row = blockIdx.x, bh = row >> 10;
    float thr = g_thr[bh];
    const float4* S = (const float4*)(g_attn + (size_t)row * NN);
    int t = threadIdx.x;
    unsigned lane = t & 31, w = t >> 5;
    __shared__ float red[8];

    float4 vv = S[t];
    float v[4] = {vv.x, vv.y, vv.z, vv.w};
    float mx = -3.0e38f;
#pragma unroll
    for (int i = 0; i < 4; i++) {
        v[i] = (v[i] <= thr) ? -1e9f : v[i];
        mx = fmaxf(mx, v[i]);
    }
#pragma unroll
    for (int o = 16; o; o >>= 1) mx = fmaxf(mx, __shfl_xor_sync(0xffffffffu, mx, o));
    if (lane == 0) red[w] = mx;
    __syncthreads();
    float m = red[0];
#pragma unroll
    for (int i = 1; i < 8; i++) m = fmaxf(m, red[i]);

    float s = 0.f;
#pragma unroll
    for (int i = 0; i < 4; i++) s += __expf(v[i] - m);
#pragma unroll
    for (int o = 16; o; o >>= 1) s += __shfl_xor_sync(0xffffffffu, s, o);
    __syncthreads();
    if (lane == 0) red[w] = s;
    __syncthreads();
    if (t == 0) {
        float tot = 0.f;
#pragma unroll
        for (int i = 0; i < 8; i++) tot += red[i];
        g_rowm[row] = m;
        g_rowinv[row] = 1.f / tot;
    }
}

// ---------------------------------------------------------------------------
extern "C" void kernel_launch(void* const* d_in, const int* in_sizes, int n_in,
                              void* d_out, int out_size) {
    const float* x = (const float*)d_in[0];
    const float* W_qkv = (const float*)d_in[1];
    const float* b_qkv = (const float*)d_in[2];
    const float* W_out = (const float*)d_in[3];
    const float* b_out = (const float*)d_in[4];
    float* out = (float*)d_out;

    float* qkv_p; cudaGetSymbolAddress((void**)&qkv_p, g_qkv);
    float* attn_p; cudaGetSymbolAddress((void**)&attn_p, g_attn);
    float* ao_p;  cudaGetSymbolAddress((void**)&ao_p, g_ao);

    // 0. zero hist
    sel_init<<<BH, 256>>>();
    // 1. QKV projection: [4096,768] @ W[768,2304] + bias
    mma_gemm<128, true, true, false, false><<<dim3(18, 32, 1), 256>>>(
        x, 0, 0, 768, W_qkv, 0, 0, 2304, b_qkv, qkv_p, 0, 0, 2304, 768, 1.f);
    // 2. Scores: Q @ K^T * 0.125
    mma_gemm<128, false, false, true, false><<<dim3(8, 8, BH), 256>>>(
        qkv_p, (size_t)1024 * 2304, 64, 2304,
        qkv_p + 768, (size_t)1024 * 2304, 64, 2304,
        nullptr, attn_p, (size_t)HH * 1048576, 1048576, 1024, 64, 0.125f);
    // 3. Threshold: hist + scan + segmented candidate gather + final select
    hist0<<<dim3(32, BH), 256>>>();
    scan0<<<BH, 256>>>();
    cand_seg<<<dim3(32, BH), 256>>>();
    sel_final<<<BH, 256>>>();
    // 4. Per-row softmax stats (no P materialization)
    rowstats<<<BH * NN, 256>>>();
    // 5. P @ V with softmax fused into A staging
    mma_gemm<64, true, false, false, true><<<dim3(1, 8, BH), 256>>>(
        attn_p, (size_t)HH * 1048576, 1048576, 1024,
        qkv_p + 1536, (size_t)1024 * 2304, 64, 2304,
        nullptr, ao_p, (size_t)1024 * 768, 64, 768, 1024, 1.f);
    // 6. Output projection: [4096,768] @ W[768,768] + bias
    mma_gemm<128, true, true, false, false><<<dim3(6, 32, 1), 256>>>(
        ao_p, 0, 0, 768, W_out, 0, 0, 768, b_out, out, 0, 0, 768, 768, 1.f);
}